// round 3
// baseline (speedup 1.0000x reference)
#include <cuda_runtime.h>
#include <math.h>

#define NNODES 100000
#define FIN    128
#define HID    256
#define NCLS   40
#define EMAX   1600000

// ---------------- scratch (device globals; no allocation allowed) ----------------
__device__ float g_bufA[(size_t)NNODES * HID];   // 102.4 MB
__device__ float g_bufB[(size_t)NNODES * HID];   // 102.4 MB
__device__ float g_dinv[NNODES];
__device__ int   g_hist[NNODES];
__device__ int   g_rowptr[NNODES + 1];
__device__ int   g_fill[NNODES];
__device__ int   g_col[EMAX];

__device__ __forceinline__ float* selbuf(int s) { return s ? g_bufB : g_bufA; }

// ---------------- precompute: degree, dinv, CSR by dst ----------------
__global__ void k_init() {
    int i = blockIdx.x * blockDim.x + threadIdx.x;
    if (i < NNODES) g_hist[i] = 0;
}

// edge_index is int32 (JAX x64 disabled): ei[0:E)=src, ei[E:2E)=dst
__global__ void k_hist(const int* __restrict__ ei, int E) {
    int e = blockIdx.x * blockDim.x + threadIdx.x;
    if (e < E) atomicAdd(&g_hist[ei[E + e]], 1);
}

__global__ void k_dinv() {
    int i = blockIdx.x * blockDim.x + threadIdx.x;
    if (i < NNODES) g_dinv[i] = rsqrtf((float)(g_hist[i] + 1)); // +1 self loop
}

// single-block exclusive scan of g_hist -> g_rowptr (and g_fill copy)
__global__ void k_scan(int n, int total_edges) {
    __shared__ int s[1024];
    const int t = threadIdx.x;
    const int C = (n + 1023) >> 10;
    const int lo = t * C;
    const int hi = (lo + C < n) ? lo + C : n;
    int sum = 0;
    for (int i = lo; i < hi; i++) sum += g_hist[i];
    s[t] = sum;
    __syncthreads();
    for (int off = 1; off < 1024; off <<= 1) {
        int v = (t >= off) ? s[t - off] : 0;
        __syncthreads();
        s[t] += v;
        __syncthreads();
    }
    int run = (t == 0) ? 0 : s[t - 1];
    for (int i = lo; i < hi; i++) {
        g_rowptr[i] = run;
        g_fill[i] = run;
        run += g_hist[i];
    }
    if (t == 1023) g_rowptr[n] = total_edges;
}

__global__ void k_scatter(const int* __restrict__ ei, int E) {
    int e = blockIdx.x * blockDim.x + threadIdx.x;
    if (e < E) {
        int d = ei[E + e];
        int pos = atomicAdd(&g_fill[d], 1);
        g_col[pos] = ei[e];
    }
}

// ---------------- aggregate: out[i] = dinv[i]*( sum_{s in N(i)} dinv[s]*in[s] + dinv[i]*in[i] ) ----------------
// one warp per node; F in {128, 256}; optional bias + relu.
// src_sel: -1 -> ext_in, 0 -> g_bufA, 1 -> g_bufB.  dst_sel: 0/1 scratch.
template <int F, bool BIAS, bool RELU>
__global__ void k_agg(const float* __restrict__ ext_in, int src_sel, int dst_sel,
                      const float* __restrict__ bias) {
    const float* in = (src_sel < 0) ? ext_in : selbuf(src_sel);
    float* out = selbuf(dst_sel);

    const int wid = (blockIdx.x * blockDim.x + threadIdx.x) >> 5;
    if (wid >= NNODES) return;
    const int lane = threadIdx.x & 31;
    constexpr int V = F / 128;  // float4 per lane
    float4 acc[V];
#pragma unroll
    for (int v = 0; v < V; v++) acc[v] = make_float4(0.f, 0.f, 0.f, 0.f);

    const int beg = g_rowptr[wid];
    const int end = g_rowptr[wid + 1];
    for (int base = beg; base < end; base += 32) {
        const int nrem = end - base;
        int idx = 0;
        float w = 0.f;
        if (lane < nrem) {
            idx = g_col[base + lane];
            w = g_dinv[idx];
        }
        const int m = nrem < 32 ? nrem : 32;
        for (int j = 0; j < m; j++) {
            const int s = __shfl_sync(0xffffffffu, idx, j);
            const float ww = __shfl_sync(0xffffffffu, w, j);
            const float4* row = reinterpret_cast<const float4*>(in + (size_t)s * F);
#pragma unroll
            for (int v = 0; v < V; v++) {
                float4 x = row[lane + v * 32];
                acc[v].x += ww * x.x;
                acc[v].y += ww * x.y;
                acc[v].z += ww * x.z;
                acc[v].w += ww * x.w;
            }
        }
    }
    const float di = g_dinv[wid];
    const float4* self = reinterpret_cast<const float4*>(in + (size_t)wid * F);
#pragma unroll
    for (int v = 0; v < V; v++) {
        float4 x = self[lane + v * 32];
        acc[v].x += di * x.x;
        acc[v].y += di * x.y;
        acc[v].z += di * x.z;
        acc[v].w += di * x.w;
    }
    float4* orow = reinterpret_cast<float4*>(out + (size_t)wid * F);
#pragma unroll
    for (int v = 0; v < V; v++) {
        float4 r;
        r.x = di * acc[v].x;
        r.y = di * acc[v].y;
        r.z = di * acc[v].z;
        r.w = di * acc[v].w;
        if (BIAS) {
            const int c = (lane + v * 32) * 4;
            r.x += bias[c + 0];
            r.y += bias[c + 1];
            r.z += bias[c + 2];
            r.w += bias[c + 3];
        }
        if (RELU) {
            r.x = fmaxf(r.x, 0.f);
            r.y = fmaxf(r.y, 0.f);
            r.z = fmaxf(r.z, 0.f);
            r.w = fmaxf(r.w, 0.f);
        }
        orow[lane + v * 32] = r;
    }
}

// aggregate F=40 + bias + log_softmax (final layer); input from scratch sel, output external
__global__ void k_agg40_lsm(int src_sel, float* __restrict__ out,
                            const float* __restrict__ bias) {
    const float* in = selbuf(src_sel);
    const int wid = (blockIdx.x * blockDim.x + threadIdx.x) >> 5;
    if (wid >= NNODES) return;
    const int lane = threadIdx.x & 31;
    const bool has2 = lane < (NCLS - 32);  // lanes 0..7 hold a second column

    float a0 = 0.f, a1 = 0.f;
    const int beg = g_rowptr[wid];
    const int end = g_rowptr[wid + 1];
    for (int base = beg; base < end; base += 32) {
        const int nrem = end - base;
        int idx = 0;
        float w = 0.f;
        if (lane < nrem) {
            idx = g_col[base + lane];
            w = g_dinv[idx];
        }
        const int m = nrem < 32 ? nrem : 32;
        for (int j = 0; j < m; j++) {
            const int s = __shfl_sync(0xffffffffu, idx, j);
            const float ww = __shfl_sync(0xffffffffu, w, j);
            a0 += ww * in[(size_t)s * NCLS + lane];
            if (has2) a1 += ww * in[(size_t)s * NCLS + 32 + lane];
        }
    }
    const float di = g_dinv[wid];
    a0 += di * in[(size_t)wid * NCLS + lane];
    if (has2) a1 += di * in[(size_t)wid * NCLS + 32 + lane];

    a0 = di * a0 + bias[lane];
    a1 = has2 ? (di * a1 + bias[32 + lane]) : -INFINITY;

    // log_softmax over 40 values in the warp
    float mx = fmaxf(a0, a1);
#pragma unroll
    for (int off = 16; off; off >>= 1) mx = fmaxf(mx, __shfl_xor_sync(0xffffffffu, mx, off));
    float se = expf(a0 - mx) + (has2 ? expf(a1 - mx) : 0.f);
#pragma unroll
    for (int off = 16; off; off >>= 1) se += __shfl_xor_sync(0xffffffffu, se, off);
    const float lse = logf(se) + mx;

    out[(size_t)wid * NCLS + lane] = a0 - lse;
    if (has2) out[(size_t)wid * NCLS + 32 + lane] = a1 - lse;
}

// ---------------- fp32 tiled GEMM: C[M,NOUT] = A[M,K] @ W[K,NOUT] (+bias, relu) ----------------
template <int K, int NOUT, bool EPI>
__global__ void k_gemm(int src_sel, const float* __restrict__ W,
                       const float* __restrict__ bias, int dst_sel) {
    const float* A = selbuf(src_sel);
    float* C = selbuf(dst_sel);

    constexpr int BM = 128, BN = 64, BK = 32;
    __shared__ float As[BK][BM];
    __shared__ float Bs[BK][BN];
    const int tid = threadIdx.x;
    const int tx = tid & 15;   // 16 col-threads
    const int ty = tid >> 4;   // 16 row-threads
    const int m0 = blockIdx.x * BM;
    const int n0 = blockIdx.y * BN;

    float acc[8][4];
#pragma unroll
    for (int i = 0; i < 8; i++)
#pragma unroll
        for (int j = 0; j < 4; j++) acc[i][j] = 0.f;

    for (int k0 = 0; k0 < K; k0 += BK) {
        // A tile: 128x32 = 1024 float4 loads, 4 per thread, stored transposed
#pragma unroll
        for (int l = 0; l < 4; l++) {
            const int lin = tid + l * 256;
            const int r = lin >> 3;
            const int c4 = lin & 7;
            float4 v = make_float4(0.f, 0.f, 0.f, 0.f);
            const int gr = m0 + r;
            if (gr < NNODES)
                v = *reinterpret_cast<const float4*>(A + (size_t)gr * K + k0 + c4 * 4);
            As[c4 * 4 + 0][r] = v.x;
            As[c4 * 4 + 1][r] = v.y;
            As[c4 * 4 + 2][r] = v.z;
            As[c4 * 4 + 3][r] = v.w;
        }
        // B tile: 32x64 = 512 float4 loads, 2 per thread
#pragma unroll
        for (int l = 0; l < 2; l++) {
            const int lin = tid + l * 256;
            const int r = lin >> 4;
            const int c4 = lin & 15;
            float4 v = make_float4(0.f, 0.f, 0.f, 0.f);
            const int gc = n0 + c4 * 4;
            if (gc < NOUT)
                v = *reinterpret_cast<const float4*>(W + (size_t)(k0 + r) * NOUT + gc);
            *reinterpret_cast<float4*>(&Bs[r][c4 * 4]) = v;
        }
        __syncthreads();
#pragma unroll
        for (int kk = 0; kk < BK; kk++) {
            float a[8];
#pragma unroll
            for (int i = 0; i < 8; i++) a[i] = As[kk][ty * 8 + i];
            const float4 b = *reinterpret_cast<const float4*>(&Bs[kk][tx * 4]);
            const float bb[4] = {b.x, b.y, b.z, b.w};
#pragma unroll
            for (int i = 0; i < 8; i++)
#pragma unroll
                for (int j = 0; j < 4; j++) acc[i][j] += a[i] * bb[j];
        }
        __syncthreads();
    }

#pragma unroll
    for (int i = 0; i < 8; i++) {
        const int m = m0 + ty * 8 + i;
        if (m >= NNODES) continue;
#pragma unroll
        for (int j = 0; j < 4; j++) {
            const int c = n0 + tx * 4 + j;
            if (c >= NOUT) continue;
            float v = acc[i][j];
            if (EPI) {
                v += bias[c];
                v = fmaxf(v, 0.f);
            }
            C[(size_t)m * NOUT + c] = v;
        }
    }
}

// ---------------- launch ----------------
extern "C" void kernel_launch(void* const* d_in, const int* in_sizes, int n_in,
                              void* d_out, int out_size) {
    const float* x = (const float*)d_in[0];
    const int* ei = (const int*)d_in[1];   // int32! (JAX x64 disabled)
    const float* W1 = (const float*)d_in[2];
    const float* b1 = (const float*)d_in[3];
    const float* W2 = (const float*)d_in[4];
    const float* b2 = (const float*)d_in[5];
    const float* W3 = (const float*)d_in[6];
    const float* b3 = (const float*)d_in[7];
    const float* W4 = (const float*)d_in[8];
    const float* b4 = (const float*)d_in[9];
    float* out = (float*)d_out;
    const int E = in_sizes[1] / 2;

    // graph structure precompute
    k_init<<<(NNODES + 255) / 256, 256>>>();
    k_hist<<<(E + 255) / 256, 256>>>(ei, E);
    k_scan<<<1, 1024>>>(NNODES, E);
    k_dinv<<<(NNODES + 255) / 256, 256>>>();
    k_scatter<<<(E + 255) / 256, 256>>>(ei, E);

    const int AGG_BLOCKS = (NNODES + 7) / 8;  // 8 warps/block
    const dim3 G1((NNODES + 127) / 128, (HID + 63) / 64);
    const dim3 G5((NNODES + 127) / 128, 1);

    // buffers: 0 = g_bufA, 1 = g_bufB, -1 = external
    // conv1: aggregate first (F=128 saves gather bytes), then GEMM + bias + relu
    k_agg<128, false, false><<<AGG_BLOCKS, 256>>>(x, -1, 0, nullptr);       // x -> A
    k_gemm<128, 256, true><<<G1, 256>>>(0, W1, b1, 1);                      // A -> B

    // conv2: GEMM, then aggregate + bias + relu
    k_gemm<256, 256, false><<<G1, 256>>>(1, W2, nullptr, 0);                // B -> A
    k_agg<256, true, true><<<AGG_BLOCKS, 256>>>(nullptr, 0, 1, b2);         // A -> B

    // conv3 (reuses W2/b2)
    k_gemm<256, 256, false><<<G1, 256>>>(1, W2, nullptr, 0);
    k_agg<256, true, true><<<AGG_BLOCKS, 256>>>(nullptr, 0, 1, b2);

    // conv4
    k_gemm<256, 256, false><<<G1, 256>>>(1, W3, nullptr, 0);
    k_agg<256, true, true><<<AGG_BLOCKS, 256>>>(nullptr, 0, 1, b3);

    // conv5: GEMM to 40 classes, aggregate + bias + log_softmax
    k_gemm<256, 40, false><<<G5, 256>>>(1, W4, nullptr, 0);
    k_agg40_lsm<<<AGG_BLOCKS, 256>>>(0, out, b4);
}